// round 1
// baseline (speedup 1.0000x reference)
#include <cuda_runtime.h>
#include <math.h>

// Problem dims (fixed by the reference)
#define Tn 2048
#define Bn 2
#define En 1024
#define Hn 16
#define Dn 64
#define BHn 32          // B*H
#define Pn 3072         // 3*E

// Scratch: __device__ globals (allocation-free, graph-capturable)
__device__ float g_q[(size_t)BHn * Tn * Dn];
__device__ float g_k[(size_t)BHn * Tn * Dn];
__device__ float g_v[(size_t)BHn * Tn * Dn];
__device__ float g_ctx[(size_t)Bn * Tn * En];

// ---------------------------------------------------------------------------
// Kernel 1: QKV projection GEMM.
//   A = x flattened (T*B = 4096, E = 1024), row-major (x is (T,B,E) contiguous)
//   W = in_proj_w (1024, 3072)
//   Output scattered into g_q/g_k/g_v with layout (b*H+h, t, d).
// Classic 128x128x8 SGEMM tile, 8x8 per thread, 256 threads.
// ---------------------------------------------------------------------------
__global__ __launch_bounds__(256) void qkv_gemm_kernel(
    const float* __restrict__ A, const float* __restrict__ W,
    const float* __restrict__ bias) {
  __shared__ float As[8][128];  // transposed: As[k][m]
  __shared__ float Bs[8][128];  // Bs[k][n]
  const int tid = threadIdx.x;
  const int tm = tid >> 4;         // 0..15
  const int tn = tid & 15;         // 0..15
  const int bm0 = blockIdx.y * 128;
  const int bn0 = blockIdx.x * 128;
  const int arow = tid >> 1;       // 0..127
  const int aseg = (tid & 1) * 4;  // 0 or 4
  const int brow = tid >> 5;       // 0..7
  const int bcol = (tid & 31) * 4; // 0..124

  float acc[8][8];
#pragma unroll
  for (int i = 0; i < 8; i++)
#pragma unroll
    for (int j = 0; j < 8; j++) acc[i][j] = 0.f;

  for (int k0 = 0; k0 < En; k0 += 8) {
    float4 a4 = *(const float4*)(A + (size_t)(bm0 + arow) * En + k0 + aseg);
    As[aseg + 0][arow] = a4.x;
    As[aseg + 1][arow] = a4.y;
    As[aseg + 2][arow] = a4.z;
    As[aseg + 3][arow] = a4.w;
    *(float4*)(&Bs[brow][bcol]) =
        *(const float4*)(W + (size_t)(k0 + brow) * Pn + bn0 + bcol);
    __syncthreads();
#pragma unroll
    for (int kk = 0; kk < 8; kk++) {
      float a[8], b[8];
      *(float4*)(a)     = *(float4*)(&As[kk][tm * 8]);
      *(float4*)(a + 4) = *(float4*)(&As[kk][tm * 8 + 4]);
      *(float4*)(b)     = *(float4*)(&Bs[kk][tn * 8]);
      *(float4*)(b + 4) = *(float4*)(&Bs[kk][tn * 8 + 4]);
#pragma unroll
      for (int i = 0; i < 8; i++)
#pragma unroll
        for (int j = 0; j < 8; j++) acc[i][j] = fmaf(a[i], b[j], acc[i][j]);
    }
    __syncthreads();
  }

  // Epilogue: scatter into q/k/v with layout ((b*H+h), t, d).
  // f = bn0 + tn*8 + j. Since tn*8 is a multiple of 8 and 8 | 64, the 8
  // consecutive f values share the same `which` (q/k/v) and head h.
  const int f0 = bn0 + tn * 8;
  const int which = f0 >> 10;
  const int fr0 = f0 & 1023;
  const int h = fr0 >> 6;
  const int d0 = fr0 & 63;
  float* dst = (which == 0) ? g_q : (which == 1) ? g_k : g_v;
#pragma unroll
  for (int i = 0; i < 8; i++) {
    const int r = bm0 + tm * 8 + i;   // row in (T*B): r = t*B + b
    const int t = r >> 1;
    const int b = r & 1;
    float o[8];
#pragma unroll
    for (int j = 0; j < 8; j++) o[j] = acc[i][j] + bias[f0 + j];
    const size_t base = ((size_t)(b * Hn + h) * Tn + t) * Dn + d0;
    *(float4*)(dst + base)     = make_float4(o[0], o[1], o[2], o[3]);
    *(float4*)(dst + base + 4) = make_float4(o[4], o[5], o[6], o[7]);
  }
}

// ---------------------------------------------------------------------------
// Kernel 2: flash-style attention, one (head, 64-query tile) per block.
// 256 threads, each owns a 4x4 micro-tile. Online softmax over 64-key tiles.
// Output written directly in the reference's "no transpose-back" scrambled
// layout: ctx[b][h*128 + t/16][(t&15)*64 + d].
// ---------------------------------------------------------------------------
#define KT_STRIDE 68  // KsT row pad: 68*4B = 272B, 16B-aligned for float4 reads

__global__ __launch_bounds__(256) void attn_kernel() {
  extern __shared__ float sm[];
  float* Qs  = sm;                        // [64][64]
  float* KsT = Qs + 64 * 64;              // [64][KT_STRIDE]  (KsT[d][kt])
  float* Vs  = KsT + 64 * KT_STRIDE;      // [64][64]         (Vs[kt][d])
  float* Ps  = Vs + 64 * 64;              // [64][64]

  const int tid = threadIdx.x;
  const int ty = tid >> 4;   // 0..15 -> query rows 4*ty..4*ty+3
  const int tx = tid & 15;   // 0..15 -> key cols / d cols 4*tx..4*tx+3
  const int bh = blockIdx.y;           // 0..31
  const int q0 = blockIdx.x * 64;

  const float* qb = g_q + (size_t)bh * Tn * Dn;
  const float* kb = g_k + (size_t)bh * Tn * Dn;
  const float* vb = g_v + (size_t)bh * Tn * Dn;

  // Load Q tile (contiguous copy)
  {
    const float4* src = (const float4*)(qb + (size_t)q0 * Dn);
    float4* dst = (float4*)Qs;
#pragma unroll
    for (int i = tid; i < 64 * 64 / 4; i += 256) dst[i] = src[i];
  }

  float acc[4][4];
  float m_i[4], l_i[4];
#pragma unroll
  for (int i = 0; i < 4; i++) {
    m_i[i] = -1e30f;
    l_i[i] = 0.f;
#pragma unroll
    for (int j = 0; j < 4; j++) acc[i][j] = 0.f;
  }

  for (int j0 = 0; j0 < Tn; j0 += 64) {
    __syncthreads();  // previous iteration done reading KsT/Vs
    // Load K tile transposed: KsT[d][kt]
#pragma unroll
    for (int i = 0; i < 16; i++) {
      int e = tid + i * 256;
      int kt = e >> 6, d = e & 63;
      KsT[d * KT_STRIDE + kt] = kb[(size_t)(j0 + kt) * Dn + d];
    }
    // Load V tile natural: Vs[kt][d]
    {
      const float4* src = (const float4*)(vb + (size_t)j0 * Dn);
      float4* dst = (float4*)Vs;
#pragma unroll
      for (int i = tid; i < 1024; i += 256) dst[i] = src[i];
    }
    __syncthreads();

    // S = (Q K^T) * 1/8  for this 64x64 tile
    float s[4][4];
#pragma unroll
    for (int i = 0; i < 4; i++)
#pragma unroll
      for (int j = 0; j < 4; j++) s[i][j] = 0.f;

#pragma unroll 4
    for (int d = 0; d < 64; d++) {
      float4 kv = *(float4*)(&KsT[d * KT_STRIDE + tx * 4]);
      float qv[4];
#pragma unroll
      for (int i = 0; i < 4; i++) qv[i] = Qs[(ty * 4 + i) * 64 + d];
#pragma unroll
      for (int i = 0; i < 4; i++) {
        s[i][0] = fmaf(qv[i], kv.x, s[i][0]);
        s[i][1] = fmaf(qv[i], kv.y, s[i][1]);
        s[i][2] = fmaf(qv[i], kv.z, s[i][2]);
        s[i][3] = fmaf(qv[i], kv.w, s[i][3]);
      }
    }
#pragma unroll
    for (int i = 0; i < 4; i++)
#pragma unroll
      for (int j = 0; j < 4; j++) s[i][j] *= 0.125f;  // D^-0.5 = 1/8

    // Online softmax per query row (row = 16 lanes sharing ty)
#pragma unroll
    for (int i = 0; i < 4; i++) {
      float v = fmaxf(fmaxf(s[i][0], s[i][1]), fmaxf(s[i][2], s[i][3]));
#pragma unroll
      for (int o = 8; o >= 1; o >>= 1)
        v = fmaxf(v, __shfl_xor_sync(0xffffffffu, v, o, 16));
      float mnew = fmaxf(m_i[i], v);
      float corr = __expf(m_i[i] - mnew);
      m_i[i] = mnew;
      float rs = 0.f;
#pragma unroll
      for (int j = 0; j < 4; j++) {
        float p = __expf(s[i][j] - mnew);
        s[i][j] = p;
        rs += p;
      }
#pragma unroll
      for (int o = 8; o >= 1; o >>= 1)
        rs += __shfl_xor_sync(0xffffffffu, rs, o, 16);
      l_i[i] = l_i[i] * corr + rs;
#pragma unroll
      for (int j = 0; j < 4; j++) acc[i][j] *= corr;
    }

    // Stage P into smem, then O += P @ V
#pragma unroll
    for (int i = 0; i < 4; i++)
      *(float4*)(&Ps[(ty * 4 + i) * 64 + tx * 4]) =
          make_float4(s[i][0], s[i][1], s[i][2], s[i][3]);
    __syncthreads();

#pragma unroll 4
    for (int c = 0; c < 64; c++) {
      float4 vv = *(float4*)(&Vs[c * 64 + tx * 4]);
      float pv[4];
#pragma unroll
      for (int i = 0; i < 4; i++) pv[i] = Ps[(ty * 4 + i) * 64 + c];
#pragma unroll
      for (int i = 0; i < 4; i++) {
        acc[i][0] = fmaf(pv[i], vv.x, acc[i][0]);
        acc[i][1] = fmaf(pv[i], vv.y, acc[i][1]);
        acc[i][2] = fmaf(pv[i], vv.z, acc[i][2]);
        acc[i][3] = fmaf(pv[i], vv.w, acc[i][3]);
      }
    }
  }

  // Normalize and write to ctx in the reference's scrambled layout:
  //   ctx[b][h*128 + t/16][(t&15)*64 + d]
  const int b = bh >> 4;
  const int h = bh & 15;
#pragma unroll
  for (int i = 0; i < 4; i++) {
    const float inv = 1.0f / l_i[i];
    const int t = q0 + ty * 4 + i;
    const int row = h * 128 + (t >> 4);
    const int col = ((t & 15) << 6) + tx * 4;
    float4 o4 = make_float4(acc[i][0] * inv, acc[i][1] * inv,
                            acc[i][2] * inv, acc[i][3] * inv);
    *(float4*)(&g_ctx[((size_t)(b * Tn + row)) * En + col]) = o4;
  }
}

#define ATTN_SMEM ((64 * 64 + 64 * KT_STRIDE + 64 * 64 + 64 * 64) * 4)

// ---------------------------------------------------------------------------
// Kernel 3: output projection GEMM.
//   A = g_ctx (4096, 1024), W = out_w (1024, 1024) -> d_out (4096, 1024)
// ---------------------------------------------------------------------------
__global__ __launch_bounds__(256) void out_gemm_kernel(
    const float* __restrict__ W, const float* __restrict__ bias,
    float* __restrict__ out) {
  __shared__ float As[8][128];
  __shared__ float Bs[8][128];
  const int tid = threadIdx.x;
  const int tm = tid >> 4;
  const int tn = tid & 15;
  const int bm0 = blockIdx.y * 128;
  const int bn0 = blockIdx.x * 128;
  const int arow = tid >> 1;
  const int aseg = (tid & 1) * 4;
  const int brow = tid >> 5;
  const int bcol = (tid & 31) * 4;

  float acc[8][8];
#pragma unroll
  for (int i = 0; i < 8; i++)
#pragma unroll
    for (int j = 0; j < 8; j++) acc[i][j] = 0.f;

  for (int k0 = 0; k0 < En; k0 += 8) {
    float4 a4 = *(const float4*)(g_ctx + (size_t)(bm0 + arow) * En + k0 + aseg);
    As[aseg + 0][arow] = a4.x;
    As[aseg + 1][arow] = a4.y;
    As[aseg + 2][arow] = a4.z;
    As[aseg + 3][arow] = a4.w;
    *(float4*)(&Bs[brow][bcol]) =
        *(const float4*)(W + (size_t)(k0 + brow) * En + bn0 + bcol);
    __syncthreads();
#pragma unroll
    for (int kk = 0; kk < 8; kk++) {
      float a[8], b[8];
      *(float4*)(a)     = *(float4*)(&As[kk][tm * 8]);
      *(float4*)(a + 4) = *(float4*)(&As[kk][tm * 8 + 4]);
      *(float4*)(b)     = *(float4*)(&Bs[kk][tn * 8]);
      *(float4*)(b + 4) = *(float4*)(&Bs[kk][tn * 8 + 4]);
#pragma unroll
      for (int i = 0; i < 8; i++)
#pragma unroll
        for (int j = 0; j < 8; j++) acc[i][j] = fmaf(a[i], b[j], acc[i][j]);
    }
    __syncthreads();
  }

  const int f0 = bn0 + tn * 8;
#pragma unroll
  for (int i = 0; i < 8; i++) {
    const int r = bm0 + tm * 8 + i;  // row in (B*T) = output row, already matches
    float o[8];
#pragma unroll
    for (int j = 0; j < 8; j++) o[j] = acc[i][j] + bias[f0 + j];
    float* dst = out + (size_t)r * En + f0;
    *(float4*)(dst)     = make_float4(o[0], o[1], o[2], o[3]);
    *(float4*)(dst + 4) = make_float4(o[4], o[5], o[6], o[7]);
  }
}

// ---------------------------------------------------------------------------
extern "C" void kernel_launch(void* const* d_in, const int* in_sizes, int n_in,
                              void* d_out, int out_size) {
  const float* x      = (const float*)d_in[0];  // (T, B, E)
  const float* w_in   = (const float*)d_in[1];  // (E, 3E)
  const float* b_in   = (const float*)d_in[2];  // (3E)
  const float* w_out  = (const float*)d_in[3];  // (E, E)
  const float* b_out  = (const float*)d_in[4];  // (E)
  float* out = (float*)d_out;                   // (B, T, E)

  cudaFuncSetAttribute(attn_kernel, cudaFuncAttributeMaxDynamicSharedMemorySize,
                       ATTN_SMEM);

  // 1) QKV projection: M=4096, N=3072, K=1024
  qkv_gemm_kernel<<<dim3(Pn / 128, (Tn * Bn) / 128), 256>>>(x, w_in, b_in);
  // 2) Attention: grid = (q-tiles, heads)
  attn_kernel<<<dim3(Tn / 64, BHn), 256, ATTN_SMEM>>>();
  // 3) Output projection: M=4096, N=1024, K=1024
  out_gemm_kernel<<<dim3(En / 128, (Tn * Bn) / 128), 256>>>(w_out, b_out, out);
}

// round 3
// speedup vs baseline: 1.4893x; 1.4893x over previous
#include <cuda_runtime.h>
#include <cuda_bf16.h>
#include <math.h>
#include <cstdint>

// Problem dims (fixed by the reference)
#define Tn 2048
#define Bn 2
#define En 1024
#define Hn 16
#define Dn 64
#define BHn 32          // B*H
#define Pn 3072         // 3*E
#define Kdim 1024       // K of both GEMMs
#define Mrows 4096      // T*B

// ---------------------------------------------------------------------------
// Scratch: __device__ globals (allocation-free, graph-capturable)
// ---------------------------------------------------------------------------
__device__ float g_q[(size_t)BHn * Tn * Dn];
__device__ float g_k[(size_t)BHn * Tn * Dn];
__device__ float g_v[(size_t)BHn * Tn * Dn];
__device__ float g_ctx[(size_t)Bn * Tn * En];

// bf16 hi/lo split operands
__device__ __nv_bfloat16 gx_hi[(size_t)Mrows * Kdim];
__device__ __nv_bfloat16 gx_lo[(size_t)Mrows * Kdim];
__device__ __nv_bfloat16 gwin_hi[(size_t)Pn * Kdim];   // in_proj_w^T  [N][K]
__device__ __nv_bfloat16 gwin_lo[(size_t)Pn * Kdim];
__device__ __nv_bfloat16 gwout_hi[(size_t)En * Kdim];  // out_w^T      [N][K]
__device__ __nv_bfloat16 gwout_lo[(size_t)En * Kdim];
__device__ __nv_bfloat16 gctx_hi[(size_t)Mrows * Kdim];
__device__ __nv_bfloat16 gctx_lo[(size_t)Mrows * Kdim];

// ---------------------------------------------------------------------------
// PTX helpers (sm_103-safe: HMMA mma.sync + ldmatrix + cp.async only)
// ---------------------------------------------------------------------------
__device__ __forceinline__ uint32_t smem_u32(const void* p) {
  uint32_t a;
  asm("{ .reg .u64 t; cvta.to.shared.u64 t, %1; cvt.u32.u64 %0, t; }"
      : "=r"(a) : "l"(p));
  return a;
}

#define SW128(off) ((uint32_t)(off) ^ ((((uint32_t)(off)) >> 3) & 0x70))

#define CP_ASYNC16(dst, src)                                       \
  asm volatile("cp.async.cg.shared.global [%0], [%1], 16;"         \
               :: "r"(dst), "l"(src) : "memory")
#define CP_COMMIT() asm volatile("cp.async.commit_group;" ::: "memory")
#define CP_WAIT(n) asm volatile("cp.async.wait_group %0;" :: "n"(n) : "memory")

__device__ __forceinline__ void ldmx4(uint32_t* r, uint32_t addr) {
  asm volatile(
      "ldmatrix.sync.aligned.m8n8.x4.shared.b16 {%0,%1,%2,%3}, [%4];"
      : "=r"(r[0]), "=r"(r[1]), "=r"(r[2]), "=r"(r[3]) : "r"(addr));
}

__device__ __forceinline__ void mma16816(float* c, const uint32_t* a,
                                         const uint32_t* b) {
  asm volatile(
      "mma.sync.aligned.m16n8k16.row.col.f32.bf16.bf16.f32 "
      "{%0,%1,%2,%3}, {%4,%5,%6,%7}, {%8,%9}, {%0,%1,%2,%3};"
      : "+f"(c[0]), "+f"(c[1]), "+f"(c[2]), "+f"(c[3])
      : "r"(a[0]), "r"(a[1]), "r"(a[2]), "r"(a[3]), "r"(b[0]), "r"(b[1]));
}

// ---------------------------------------------------------------------------
// Conversion kernels: fp32 -> bf16 hi/lo split
// ---------------------------------------------------------------------------
__global__ __launch_bounds__(256) void cvt_pair(const float* __restrict__ xin,
                                                int which) {
  const float* in = (which == 0) ? xin : g_ctx;
  __nv_bfloat16* hi = (which == 0) ? gx_hi : gctx_hi;
  __nv_bfloat16* lo = (which == 0) ? gx_lo : gctx_lo;
  size_t i = ((size_t)blockIdx.x * blockDim.x + threadIdx.x) * 4;
  if (i < (size_t)Mrows * Kdim) {
    float4 v = *(const float4*)(in + i);
    __nv_bfloat16 h[4], l[4];
    h[0] = __float2bfloat16(v.x); l[0] = __float2bfloat16(v.x - __bfloat162float(h[0]));
    h[1] = __float2bfloat16(v.y); l[1] = __float2bfloat16(v.y - __bfloat162float(h[1]));
    h[2] = __float2bfloat16(v.z); l[2] = __float2bfloat16(v.z - __bfloat162float(h[2]));
    h[3] = __float2bfloat16(v.w); l[3] = __float2bfloat16(v.w - __bfloat162float(h[3]));
    *(uint2*)(hi + i) = *(uint2*)h;
    *(uint2*)(lo + i) = *(uint2*)l;
  }
}

// Transpose W[K][N] -> Wt_hi/lo [N][K] (bf16 split). which: 0=in_proj, 1=out
__global__ __launch_bounds__(256) void cvt_transpose(const float* __restrict__ W,
                                                     int which) {
  __nv_bfloat16* hi = (which == 0) ? gwin_hi : gwout_hi;
  __nv_bfloat16* lo = (which == 0) ? gwin_lo : gwout_lo;
  const int N = (which == 0) ? Pn : En;
  __shared__ float t[32][33];
  const int n0 = blockIdx.x * 32, k0 = blockIdx.y * 32;
  const int tx = threadIdx.x, ty = threadIdx.y;  // 32 x 8
#pragma unroll
  for (int i = ty; i < 32; i += 8)
    t[i][tx] = W[(size_t)(k0 + i) * N + n0 + tx];
  __syncthreads();
#pragma unroll
  for (int j = ty; j < 32; j += 8) {
    float v = t[tx][j];
    __nv_bfloat16 h = __float2bfloat16(v);
    __nv_bfloat16 l = __float2bfloat16(v - __bfloat162float(h));
    hi[(size_t)(n0 + j) * Kdim + k0 + tx] = h;
    lo[(size_t)(n0 + j) * Kdim + k0 + tx] = l;
  }
}

// ---------------------------------------------------------------------------
// HMMA split-bf16 GEMM: per CTA D[128 x 128] = A[M,K] * B^T[N,K] + bias
//   mode 0: A = x split, B = in_proj^T; scatter epilogue into g_q/g_k/g_v
//   mode 1: A = ctx split, B = out_w^T; linear epilogue into d_out
// 16 K-chunks of 64, cp.async double-buffered SW128 smem, ldmatrix fragments,
// 3 accumulation passes: Ahi*Bhi + Ahi*Blo + Alo*Bhi.
// ---------------------------------------------------------------------------
#define OFF_AHI 0
#define OFF_ALO 16384
#define OFF_BHI 32768
#define OFF_BLO 49152
#define STAGE_BYTES 65536
#define GEMM_SMEM (2 * STAGE_BYTES)  // 128 KB

__device__ __forceinline__ void load_chunk_async(
    uint32_t smem_base, int stg, int kc, int m0, int n0, int tid,
    const __nv_bfloat16* __restrict__ Ahi, const __nv_bfloat16* __restrict__ Alo,
    const __nv_bfloat16* __restrict__ Bhi, const __nv_bfloat16* __restrict__ Blo) {
  const int k0 = kc * 64;
  const uint32_t sb = smem_base + stg * STAGE_BYTES;
#pragma unroll
  for (int it = 0; it < 4; it++) {  // 1024 16B-vectors per matrix / 256 thr
    int vec = tid + it * 256;
    int r = vec >> 3, seg = vec & 7;   // row 0..127, 16B-seg 0..7
    uint32_t sw = SW128(r * 128 + seg * 16);
    size_t giA = (size_t)(m0 + r) * Kdim + k0 + seg * 8;
    size_t giB = (size_t)(n0 + r) * Kdim + k0 + seg * 8;
    CP_ASYNC16(sb + OFF_AHI + sw, Ahi + giA);
    CP_ASYNC16(sb + OFF_ALO + sw, Alo + giA);
    CP_ASYNC16(sb + OFF_BHI + sw, Bhi + giB);
    CP_ASYNC16(sb + OFF_BLO + sw, Blo + giB);
  }
}

__global__ __launch_bounds__(256, 1) void hmma_gemm(
    const float* __restrict__ bias, float* __restrict__ out, int mode) {
  extern __shared__ __align__(1024) char smc[];
  const uint32_t smem_base = smem_u32(smc);
  const int tid = threadIdx.x;
  const int wid = tid >> 5;
  const int lane = tid & 31;
  const int m0 = blockIdx.y * 128;
  const int n0 = blockIdx.x * 128;
  const int wm = (wid & 1) * 64;   // warp m-offset in tile
  const int wn = (wid >> 1) * 32;  // warp n-offset in tile

  const __nv_bfloat16* Ahi = (mode == 0) ? gx_hi : gctx_hi;
  const __nv_bfloat16* Alo = (mode == 0) ? gx_lo : gctx_lo;
  const __nv_bfloat16* Bhi = (mode == 0) ? gwin_hi : gwout_hi;
  const __nv_bfloat16* Blo = (mode == 0) ? gwin_lo : gwout_lo;

  float acc[4][4][4];
#pragma unroll
  for (int i = 0; i < 4; i++)
#pragma unroll
    for (int j = 0; j < 4; j++)
#pragma unroll
      for (int c = 0; c < 4; c++) acc[i][j][c] = 0.f;

  // ldmatrix lane-address components
  const int g = lane >> 3;   // matrix id 0..3 within x4
  const int rr = lane & 7;   // row within 8x8 matrix

  load_chunk_async(smem_base, 0, 0, m0, n0, tid, Ahi, Alo, Bhi, Blo);
  CP_COMMIT();

  for (int c = 0; c < 16; c++) {
    const int buf = c & 1;
    if (c < 15) {
      load_chunk_async(smem_base, 1 - buf, c + 1, m0, n0, tid, Ahi, Alo, Bhi, Blo);
      CP_COMMIT();
      CP_WAIT(1);
    } else {
      CP_WAIT(0);
    }
    __syncthreads();

    const uint32_t sb = smem_base + buf * STAGE_BYTES;
#pragma unroll
    for (int ks = 0; ks < 4; ks++) {
      uint32_t aH[4][4], aL[4][4], bH[2][4], bL[2][4];
      // A fragments: x4 matrices = (m0-7,k0-7),(m8-15,k0-7),(m0-7,k8-15),(m8-15,k8-15)
#pragma unroll
      for (int i = 0; i < 4; i++) {
        int row = wm + i * 16 + (g & 1) * 8 + rr;
        uint32_t off = SW128(row * 128 + ks * 32 + (g >> 1) * 16);
        ldmx4(aH[i], sb + OFF_AHI + off);
        ldmx4(aL[i], sb + OFF_ALO + off);
      }
      // B fragments: x4 matrices = (k0,n j),(k8,n j),(k0,n j+1),(k8,n j+1)
#pragma unroll
      for (int jj = 0; jj < 2; jj++) {
        int row = wn + jj * 16 + (g >> 1) * 8 + rr;
        uint32_t off = SW128(row * 128 + ks * 32 + (g & 1) * 16);
        ldmx4(bH[jj], sb + OFF_BHI + off);
        ldmx4(bL[jj], sb + OFF_BLO + off);
      }
#pragma unroll
      for (int i = 0; i < 4; i++)
#pragma unroll
        for (int j = 0; j < 4; j++) {
          const uint32_t* bh = &bH[j >> 1][(j & 1) * 2];
          const uint32_t* bl = &bL[j >> 1][(j & 1) * 2];
          mma16816(acc[i][j], aH[i], bh);
          mma16816(acc[i][j], aH[i], bl);
          mma16816(acc[i][j], aL[i], bh);
        }
    }
    __syncthreads();
  }

  // Epilogue: fragment layout -> global. Lane holds (m=lane/4 [+8], n=(lane%4)*2 [+1]).
#pragma unroll
  for (int i = 0; i < 4; i++) {
#pragma unroll
    for (int j = 0; j < 4; j++) {
      const int mr = m0 + wm + i * 16 + (lane >> 2);
      const int f = n0 + wn + j * 8 + (lane & 3) * 2;
      const float b0 = bias[f], b1 = bias[f + 1];
      float2 v0 = make_float2(acc[i][j][0] + b0, acc[i][j][1] + b1);
      float2 v1 = make_float2(acc[i][j][2] + b0, acc[i][j][3] + b1);
      if (mode == 0) {
        const int which = f >> 10;
        const int h = (f & 1023) >> 6;
        const int d0 = f & 63;
        float* dst = (which == 0) ? g_q : (which == 1) ? g_k : g_v;
        const int t0 = mr >> 1, bb0 = mr & 1;
        const int t1 = (mr + 8) >> 1, bb1 = (mr + 8) & 1;
        *(float2*)(dst + ((size_t)(bb0 * Hn + h) * Tn + t0) * Dn + d0) = v0;
        *(float2*)(dst + ((size_t)(bb1 * Hn + h) * Tn + t1) * Dn + d0) = v1;
      } else {
        *(float2*)(out + (size_t)mr * En + f) = v0;
        *(float2*)(out + (size_t)(mr + 8) * En + f) = v1;
      }
    }
  }
}

// ---------------------------------------------------------------------------
// Flash-style SIMT attention (unchanged from passing round-1 kernel)
// ---------------------------------------------------------------------------
#define KT_STRIDE 68

__global__ __launch_bounds__(256) void attn_kernel() {
  extern __shared__ __align__(1024) char smc[];
  float* sm = (float*)smc;
  float* Qs = sm;
  float* KsT = Qs + 64 * 64;
  float* Vs = KsT + 64 * KT_STRIDE;
  float* Ps = Vs + 64 * 64;

  const int tid = threadIdx.x;
  const int ty = tid >> 4;
  const int tx = tid & 15;
  const int bh = blockIdx.y;
  const int q0 = blockIdx.x * 64;

  const float* qb = g_q + (size_t)bh * Tn * Dn;
  const float* kb = g_k + (size_t)bh * Tn * Dn;
  const float* vb = g_v + (size_t)bh * Tn * Dn;

  {
    const float4* src = (const float4*)(qb + (size_t)q0 * Dn);
    float4* dst = (float4*)Qs;
#pragma unroll
    for (int i = tid; i < 64 * 64 / 4; i += 256) dst[i] = src[i];
  }

  float acc[4][4];
  float m_i[4], l_i[4];
#pragma unroll
  for (int i = 0; i < 4; i++) {
    m_i[i] = -1e30f;
    l_i[i] = 0.f;
#pragma unroll
    for (int j = 0; j < 4; j++) acc[i][j] = 0.f;
  }

  for (int j0 = 0; j0 < Tn; j0 += 64) {
    __syncthreads();
#pragma unroll
    for (int i = 0; i < 16; i++) {
      int e = tid + i * 256;
      int kt = e >> 6, d = e & 63;
      KsT[d * KT_STRIDE + kt] = kb[(size_t)(j0 + kt) * Dn + d];
    }
    {
      const float4* src = (const float4*)(vb + (size_t)j0 * Dn);
      float4* dst = (float4*)Vs;
#pragma unroll
      for (int i = tid; i < 1024; i += 256) dst[i] = src[i];
    }
    __syncthreads();

    float s[4][4];
#pragma unroll
    for (int i = 0; i < 4; i++)
#pragma unroll
      for (int j = 0; j < 4; j++) s[i][j] = 0.f;

#pragma unroll 4
    for (int d = 0; d < 64; d++) {
      float4 kv = *(float4*)(&KsT[d * KT_STRIDE + tx * 4]);
      float qv[4];
#pragma unroll
      for (int i = 0; i < 4; i++) qv[i] = Qs[(ty * 4 + i) * 64 + d];
#pragma unroll
      for (int i = 0; i < 4; i++) {
        s[i][0] = fmaf(qv[i], kv.x, s[i][0]);
        s[i][1] = fmaf(qv[i], kv.y, s[i][1]);
        s[i][2] = fmaf(qv[i], kv.z, s[i][2]);
        s[i][3] = fmaf(qv[i], kv.w, s[i][3]);
      }
    }
#pragma unroll
    for (int i = 0; i < 4; i++)
#pragma unroll
      for (int j = 0; j < 4; j++) s[i][j] *= 0.125f;

#pragma unroll
    for (int i = 0; i < 4; i++) {
      float v = fmaxf(fmaxf(s[i][0], s[i][1]), fmaxf(s[i][2], s[i][3]));
#pragma unroll
      for (int o = 8; o >= 1; o >>= 1)
        v = fmaxf(v, __shfl_xor_sync(0xffffffffu, v, o, 16));
      float mnew = fmaxf(m_i[i], v);
      float corr = __expf(m_i[i] - mnew);
      m_i[i] = mnew;
      float rs = 0.f;
#pragma unroll
      for (int j = 0; j < 4; j++) {
        float p = __expf(s[i][j] - mnew);
        s[i][j] = p;
        rs += p;
      }
#pragma unroll
      for (int o = 8; o >= 1; o >>= 1)
        rs += __shfl_xor_sync(0xffffffffu, rs, o, 16);
      l_i[i] = l_i[i] * corr + rs;
#pragma unroll
      for (int j = 0; j < 4; j++) acc[i][j] *= corr;
    }

#pragma unroll
    for (int i = 0; i < 4; i++)
      *(float4*)(&Ps[(ty * 4 + i) * 64 + tx * 4]) =
          make_float4(s[i][0], s[i][1], s[i][2], s[i][3]);
    __syncthreads();

#pragma unroll 4
    for (int c = 0; c < 64; c++) {
      float4 vv = *(float4*)(&Vs[c * 64 + tx * 4]);
      float pv[4];
#pragma unroll
      for (int i = 0; i < 4; i++) pv[i] = Ps[(ty * 4 + i) * 64 + c];
#pragma unroll
      for (int i = 0; i < 4; i++) {
        acc[i][0] = fmaf(pv[i], vv.x, acc[i][0]);
        acc[i][1] = fmaf(pv[i], vv.y, acc[i][1]);
        acc[i][2] = fmaf(pv[i], vv.z, acc[i][2]);
        acc[i][3] = fmaf(pv[i], vv.w, acc[i][3]);
      }
    }
  }

  const int b = bh >> 4;
  const int h = bh & 15;
#pragma unroll
  for (int i = 0; i < 4; i++) {
    const float inv = 1.0f / l_i[i];
    const int t = q0 + ty * 4 + i;
    const int rowi = h * 128 + (t >> 4);
    const int col = ((t & 15) << 6) + tx * 4;
    float4 o4 = make_float4(acc[i][0] * inv, acc[i][1] * inv, acc[i][2] * inv,
                            acc[i][3] * inv);
    *(float4*)(&g_ctx[((size_t)(b * Tn + rowi)) * En + col]) = o4;
  }
}

#define ATTN_SMEM ((64 * 64 + 64 * KT_STRIDE + 64 * 64 + 64 * 64) * 4)

// ---------------------------------------------------------------------------
extern "C" void kernel_launch(void* const* d_in, const int* in_sizes, int n_in,
                              void* d_out, int out_size) {
  const float* x     = (const float*)d_in[0];  // (T, B, E)
  const float* w_in  = (const float*)d_in[1];  // (E, 3E)
  const float* b_in  = (const float*)d_in[2];  // (3E)
  const float* w_out = (const float*)d_in[3];  // (E, E)
  const float* b_out = (const float*)d_in[4];  // (E)
  float* out = (float*)d_out;                  // (B, T, E)

  cudaFuncSetAttribute(hmma_gemm, cudaFuncAttributeMaxDynamicSharedMemorySize,
                       GEMM_SMEM);
  cudaFuncSetAttribute(attn_kernel, cudaFuncAttributeMaxDynamicSharedMemorySize,
                       ATTN_SMEM);

  // bf16 split conversions
  cvt_pair<<<(Mrows * Kdim / 4 + 255) / 256, 256>>>(x, 0);
  cvt_transpose<<<dim3(Pn / 32, Kdim / 32), dim3(32, 8)>>>(w_in, 0);
  cvt_transpose<<<dim3(En / 32, Kdim / 32), dim3(32, 8)>>>(w_out, 1);

  // 1) QKV projection on HMMA tensor cores: M=4096, N=3072, K=1024
  hmma_gemm<<<dim3(Pn / 128, Mrows / 128), 256, GEMM_SMEM>>>(b_in, nullptr, 0);
  // 2) Attention (SIMT flash)
  attn_kernel<<<dim3(Tn / 64, BHn), 256, ATTN_SMEM>>>();
  // 3) ctx -> bf16 split, then output projection: M=4096, N=1024, K=1024
  cvt_pair<<<(Mrows * Kdim / 4 + 255) / 256, 256>>>(nullptr, 1);
  hmma_gemm<<<dim3(En / 128, Mrows / 128), 256, GEMM_SMEM>>>(b_out, out, 1);
}

// round 4
// speedup vs baseline: 3.1146x; 2.0913x over previous
#include <cuda_runtime.h>
#include <cuda_bf16.h>
#include <math.h>
#include <cstdint>

// Problem dims (fixed by the reference)
#define Tn 2048
#define Bn 2
#define En 1024
#define Hn 16
#define Dn 64
#define BHn 32          // B*H
#define Pn 3072         // 3*E
#define Kdim 1024       // K of both GEMMs
#define Mrows 4096      // T*B

// ---------------------------------------------------------------------------
// Scratch: __device__ globals (allocation-free, graph-capturable)
// ---------------------------------------------------------------------------
__device__ __nv_bfloat16 gx_hi[(size_t)Mrows * Kdim];
__device__ __nv_bfloat16 gx_lo[(size_t)Mrows * Kdim];
__device__ __nv_bfloat16 gwin_hi[(size_t)Pn * Kdim];   // in_proj_w^T  [N][K]
__device__ __nv_bfloat16 gwin_lo[(size_t)Pn * Kdim];
__device__ __nv_bfloat16 gwout_hi[(size_t)En * Kdim];  // out_w^T      [N][K]
__device__ __nv_bfloat16 gwout_lo[(size_t)En * Kdim];
__device__ __nv_bfloat16 gctx_hi[(size_t)Mrows * Kdim];
__device__ __nv_bfloat16 gctx_lo[(size_t)Mrows * Kdim];
// q/k/v splits, layout [(b*H+h)][t][d]; q pre-scaled by 0.125
__device__ __nv_bfloat16 gq_hi[(size_t)BHn * Tn * Dn];
__device__ __nv_bfloat16 gq_lo[(size_t)BHn * Tn * Dn];
__device__ __nv_bfloat16 gk_hi[(size_t)BHn * Tn * Dn];
__device__ __nv_bfloat16 gk_lo[(size_t)BHn * Tn * Dn];
__device__ __nv_bfloat16 gv_hi[(size_t)BHn * Tn * Dn];
__device__ __nv_bfloat16 gv_lo[(size_t)BHn * Tn * Dn];

// ---------------------------------------------------------------------------
// PTX helpers (sm_103-safe: mma.sync + ldmatrix + cp.async only)
// ---------------------------------------------------------------------------
__device__ __forceinline__ uint32_t smem_u32(const void* p) {
  uint32_t a;
  asm("{ .reg .u64 t; cvta.to.shared.u64 t, %1; cvt.u32.u64 %0, t; }"
      : "=r"(a) : "l"(p));
  return a;
}

#define SW128(off) ((uint32_t)(off) ^ ((((uint32_t)(off)) >> 3) & 0x70))

#define CP_ASYNC16(dst, src)                                       \
  asm volatile("cp.async.cg.shared.global [%0], [%1], 16;"         \
               :: "r"(dst), "l"(src) : "memory")
#define CP_COMMIT() asm volatile("cp.async.commit_group;" ::: "memory")
#define CP_WAIT(n) asm volatile("cp.async.wait_group %0;" :: "n"(n) : "memory")

__device__ __forceinline__ void ldmx4(uint32_t* r, uint32_t addr) {
  asm volatile(
      "ldmatrix.sync.aligned.m8n8.x4.shared.b16 {%0,%1,%2,%3}, [%4];"
      : "=r"(r[0]), "=r"(r[1]), "=r"(r[2]), "=r"(r[3]) : "r"(addr));
}
__device__ __forceinline__ void ldmx4t(uint32_t* r, uint32_t addr) {
  asm volatile(
      "ldmatrix.sync.aligned.m8n8.x4.trans.shared.b16 {%0,%1,%2,%3}, [%4];"
      : "=r"(r[0]), "=r"(r[1]), "=r"(r[2]), "=r"(r[3]) : "r"(addr));
}

__device__ __forceinline__ void mma16816(float* c, const uint32_t* a,
                                         const uint32_t* b) {
  asm volatile(
      "mma.sync.aligned.m16n8k16.row.col.f32.bf16.bf16.f32 "
      "{%0,%1,%2,%3}, {%4,%5,%6,%7}, {%8,%9}, {%0,%1,%2,%3};"
      : "+f"(c[0]), "+f"(c[1]), "+f"(c[2]), "+f"(c[3])
      : "r"(a[0]), "r"(a[1]), "r"(a[2]), "r"(a[3]), "r"(b[0]), "r"(b[1]));
}

// split a float pair into bf16 hi/lo packed words
__device__ __forceinline__ void split2(float p0, float p1, uint32_t& h,
                                       uint32_t& l) {
  __nv_bfloat162 hh = __float22bfloat162_rn(make_float2(p0, p1));
  __nv_bfloat162 ll = __float22bfloat162_rn(
      make_float2(p0 - __bfloat162float(hh.x), p1 - __bfloat162float(hh.y)));
  h = *(uint32_t*)&hh;
  l = *(uint32_t*)&ll;
}

// ---------------------------------------------------------------------------
// Conversion kernels: fp32 -> bf16 hi/lo split
// ---------------------------------------------------------------------------
__global__ __launch_bounds__(256) void cvt_x(const float* __restrict__ xin) {
  size_t i = ((size_t)blockIdx.x * blockDim.x + threadIdx.x) * 4;
  if (i < (size_t)Mrows * Kdim) {
    float4 v = *(const float4*)(xin + i);
    __nv_bfloat16 h[4], l[4];
    h[0] = __float2bfloat16(v.x); l[0] = __float2bfloat16(v.x - __bfloat162float(h[0]));
    h[1] = __float2bfloat16(v.y); l[1] = __float2bfloat16(v.y - __bfloat162float(h[1]));
    h[2] = __float2bfloat16(v.z); l[2] = __float2bfloat16(v.z - __bfloat162float(h[2]));
    h[3] = __float2bfloat16(v.w); l[3] = __float2bfloat16(v.w - __bfloat162float(h[3]));
    *(uint2*)(gx_hi + i) = *(uint2*)h;
    *(uint2*)(gx_lo + i) = *(uint2*)l;
  }
}

// Transpose W[K][N] -> Wt_hi/lo [N][K] (bf16 split). which: 0=in_proj, 1=out
__global__ __launch_bounds__(256) void cvt_transpose(const float* __restrict__ W,
                                                     int which) {
  __nv_bfloat16* hi = (which == 0) ? gwin_hi : gwout_hi;
  __nv_bfloat16* lo = (which == 0) ? gwin_lo : gwout_lo;
  const int N = (which == 0) ? Pn : En;
  __shared__ float t[32][33];
  const int n0 = blockIdx.x * 32, k0 = blockIdx.y * 32;
  const int tx = threadIdx.x, ty = threadIdx.y;  // 32 x 8
#pragma unroll
  for (int i = ty; i < 32; i += 8)
    t[i][tx] = W[(size_t)(k0 + i) * N + n0 + tx];
  __syncthreads();
#pragma unroll
  for (int j = ty; j < 32; j += 8) {
    float v = t[tx][j];
    __nv_bfloat16 h = __float2bfloat16(v);
    __nv_bfloat16 l = __float2bfloat16(v - __bfloat162float(h));
    hi[(size_t)(n0 + j) * Kdim + k0 + tx] = h;
    lo[(size_t)(n0 + j) * Kdim + k0 + tx] = l;
  }
}

// ---------------------------------------------------------------------------
// HMMA split-bf16 GEMM: per CTA D[128 x 128] = A[M,K] * B^T[N,K] + bias
//   mode 0: A = x split, B = in_proj^T; epilogue -> q/k/v bf16 splits
//   mode 1: A = ctx split, B = out_w^T; epilogue -> fp32 d_out
// ---------------------------------------------------------------------------
#define OFF_AHI 0
#define OFF_ALO 16384
#define OFF_BHI 32768
#define OFF_BLO 49152
#define STAGE_BYTES 65536
#define GEMM_SMEM (2 * STAGE_BYTES)  // 128 KB

__device__ __forceinline__ void load_chunk_async(
    uint32_t smem_base, int stg, int kc, int m0, int n0, int tid,
    const __nv_bfloat16* __restrict__ Ahi, const __nv_bfloat16* __restrict__ Alo,
    const __nv_bfloat16* __restrict__ Bhi, const __nv_bfloat16* __restrict__ Blo) {
  const int k0 = kc * 64;
  const uint32_t sb = smem_base + stg * STAGE_BYTES;
#pragma unroll
  for (int it = 0; it < 4; it++) {
    int vec = tid + it * 256;
    int r = vec >> 3, seg = vec & 7;
    uint32_t sw = SW128(r * 128 + seg * 16);
    size_t giA = (size_t)(m0 + r) * Kdim + k0 + seg * 8;
    size_t giB = (size_t)(n0 + r) * Kdim + k0 + seg * 8;
    CP_ASYNC16(sb + OFF_AHI + sw, Ahi + giA);
    CP_ASYNC16(sb + OFF_ALO + sw, Alo + giA);
    CP_ASYNC16(sb + OFF_BHI + sw, Bhi + giB);
    CP_ASYNC16(sb + OFF_BLO + sw, Blo + giB);
  }
}

__global__ __launch_bounds__(256, 1) void hmma_gemm(
    const float* __restrict__ bias, float* __restrict__ out, int mode) {
  extern __shared__ __align__(1024) char smc[];
  const uint32_t smem_base = smem_u32(smc);
  const int tid = threadIdx.x;
  const int wid = tid >> 5;
  const int lane = tid & 31;
  const int m0 = blockIdx.y * 128;
  const int n0 = blockIdx.x * 128;
  const int wm = (wid & 1) * 64;
  const int wn = (wid >> 1) * 32;

  const __nv_bfloat16* Ahi = (mode == 0) ? gx_hi : gctx_hi;
  const __nv_bfloat16* Alo = (mode == 0) ? gx_lo : gctx_lo;
  const __nv_bfloat16* Bhi = (mode == 0) ? gwin_hi : gwout_hi;
  const __nv_bfloat16* Blo = (mode == 0) ? gwin_lo : gwout_lo;

  float acc[4][4][4];
#pragma unroll
  for (int i = 0; i < 4; i++)
#pragma unroll
    for (int j = 0; j < 4; j++)
#pragma unroll
      for (int c = 0; c < 4; c++) acc[i][j][c] = 0.f;

  const int g = lane >> 3;
  const int rr = lane & 7;

  load_chunk_async(smem_base, 0, 0, m0, n0, tid, Ahi, Alo, Bhi, Blo);
  CP_COMMIT();

  for (int c = 0; c < 16; c++) {
    const int buf = c & 1;
    if (c < 15) {
      load_chunk_async(smem_base, 1 - buf, c + 1, m0, n0, tid, Ahi, Alo, Bhi, Blo);
      CP_COMMIT();
      CP_WAIT(1);
    } else {
      CP_WAIT(0);
    }
    __syncthreads();

    const uint32_t sb = smem_base + buf * STAGE_BYTES;
#pragma unroll
    for (int ks = 0; ks < 4; ks++) {
      uint32_t aH[4][4], aL[4][4], bH[2][4], bL[2][4];
#pragma unroll
      for (int i = 0; i < 4; i++) {
        int row = wm + i * 16 + (g & 1) * 8 + rr;
        uint32_t off = SW128(row * 128 + ks * 32 + (g >> 1) * 16);
        ldmx4(aH[i], sb + OFF_AHI + off);
        ldmx4(aL[i], sb + OFF_ALO + off);
      }
#pragma unroll
      for (int jj = 0; jj < 2; jj++) {
        int row = wn + jj * 16 + (g >> 1) * 8 + rr;
        uint32_t off = SW128(row * 128 + ks * 32 + (g & 1) * 16);
        ldmx4(bH[jj], sb + OFF_BHI + off);
        ldmx4(bL[jj], sb + OFF_BLO + off);
      }
#pragma unroll
      for (int i = 0; i < 4; i++)
#pragma unroll
        for (int j = 0; j < 4; j++) {
          const uint32_t* bh = &bH[j >> 1][(j & 1) * 2];
          const uint32_t* bl = &bL[j >> 1][(j & 1) * 2];
          mma16816(acc[i][j], aH[i], bh);
          mma16816(acc[i][j], aH[i], bl);
          mma16816(acc[i][j], aL[i], bh);
        }
    }
    __syncthreads();
  }

  // Epilogue
#pragma unroll
  for (int i = 0; i < 4; i++) {
#pragma unroll
    for (int j = 0; j < 4; j++) {
      const int mr = m0 + wm + i * 16 + (lane >> 2);
      const int f = n0 + wn + j * 8 + (lane & 3) * 2;
      const float b0 = bias[f], b1 = bias[f + 1];
      float p00 = acc[i][j][0] + b0, p01 = acc[i][j][1] + b1;
      float p10 = acc[i][j][2] + b0, p11 = acc[i][j][3] + b1;
      if (mode == 0) {
        const int which = f >> 10;
        const int h = (f & 1023) >> 6;
        const int d0 = f & 63;
        __nv_bfloat16 *dh, *dl;
        float scale = 1.f;
        if (which == 0) { dh = gq_hi; dl = gq_lo; scale = 0.125f; }
        else if (which == 1) { dh = gk_hi; dl = gk_lo; }
        else { dh = gv_hi; dl = gv_lo; }
        p00 *= scale; p01 *= scale; p10 *= scale; p11 *= scale;
        uint32_t h0, l0, h1, l1;
        split2(p00, p01, h0, l0);
        split2(p10, p11, h1, l1);
        const int t0 = mr >> 1, bb0 = mr & 1;
        const int t1 = (mr + 8) >> 1, bb1 = (mr + 8) & 1;
        size_t i0 = ((size_t)(bb0 * Hn + h) * Tn + t0) * Dn + d0;
        size_t i1 = ((size_t)(bb1 * Hn + h) * Tn + t1) * Dn + d0;
        *(uint32_t*)(dh + i0) = h0; *(uint32_t*)(dl + i0) = l0;
        *(uint32_t*)(dh + i1) = h1; *(uint32_t*)(dl + i1) = l1;
      } else {
        *(float2*)(out + (size_t)mr * En + f) = make_float2(p00, p01);
        *(float2*)(out + (size_t)(mr + 8) * En + f) = make_float2(p10, p11);
      }
    }
  }
}

// ---------------------------------------------------------------------------
// HMMA flash attention: per CTA 128 queries x 1 head; 8 warps x 16 rows.
// K/V in 64-key chunks (hi/lo), double-buffered cp.async SW128 smem.
// S = Qs*K^T (3-pass split, Q pre-scaled 1/8), warp-local online softmax,
// O += P*V (3-pass split, P frags straight from S accumulators).
// Output written as bf16 hi/lo ctx in the reference's scrambled layout.
// ---------------------------------------------------------------------------
#define A_OFF_KHI 0
#define A_OFF_KLO 8192
#define A_OFF_VHI 16384
#define A_OFF_VLO 24576
#define A_STAGE 32768
#define A_OFF_QHI 65536
#define A_OFF_QLO 81920
#define ATTN_SMEM 98304

__device__ __forceinline__ void attn_load_chunk(uint32_t sb, int stg, int j0,
                                                int tid,
                                                const __nv_bfloat16* kh,
                                                const __nv_bfloat16* kl,
                                                const __nv_bfloat16* vh,
                                                const __nv_bfloat16* vl) {
  const uint32_t base = sb + stg * A_STAGE;
#pragma unroll
  for (int it = 0; it < 2; it++) {
    int vec = tid + it * 256;       // 0..511
    int r = vec >> 3, seg = vec & 7;
    uint32_t sw = SW128(r * 128 + seg * 16);
    size_t gi = ((size_t)(j0 + r)) * Dn + seg * 8;
    CP_ASYNC16(base + A_OFF_KHI + sw, kh + gi);
    CP_ASYNC16(base + A_OFF_KLO + sw, kl + gi);
    CP_ASYNC16(base + A_OFF_VHI + sw, vh + gi);
    CP_ASYNC16(base + A_OFF_VLO + sw, vl + gi);
  }
}

__global__ __launch_bounds__(256, 1) void attn_hmma() {
  extern __shared__ __align__(1024) char smc[];
  const uint32_t sb = smem_u32(smc);
  const int tid = threadIdx.x;
  const int wid = tid >> 5;
  const int lane = tid & 31;
  const int g = lane >> 3;
  const int rr = lane & 7;
  const int bh = blockIdx.y;
  const int q0 = blockIdx.x * 128;

  const __nv_bfloat16* qh = gq_hi + (size_t)bh * Tn * Dn;
  const __nv_bfloat16* ql = gq_lo + (size_t)bh * Tn * Dn;
  const __nv_bfloat16* kh = gk_hi + (size_t)bh * Tn * Dn;
  const __nv_bfloat16* kl = gk_lo + (size_t)bh * Tn * Dn;
  const __nv_bfloat16* vh = gv_hi + (size_t)bh * Tn * Dn;
  const __nv_bfloat16* vl = gv_lo + (size_t)bh * Tn * Dn;

  // Preamble: Q tile (hi/lo) + chunk 0, one commit group.
#pragma unroll
  for (int it = 0; it < 4; it++) {
    int vec = tid + it * 256;       // 0..1023
    int r = vec >> 3, seg = vec & 7;
    uint32_t sw = SW128(r * 128 + seg * 16);
    size_t gi = ((size_t)(q0 + r)) * Dn + seg * 8;
    CP_ASYNC16(sb + A_OFF_QHI + sw, qh + gi);
    CP_ASYNC16(sb + A_OFF_QLO + sw, ql + gi);
  }
  attn_load_chunk(sb, 0, 0, tid, kh, kl, vh, vl);
  CP_COMMIT();
  CP_WAIT(0);
  __syncthreads();

  // Q fragments held in registers for the whole key loop
  uint32_t qH[4][4], qL[4][4];
#pragma unroll
  for (int ks = 0; ks < 4; ks++) {
    int row = wid * 16 + (g & 1) * 8 + rr;
    uint32_t off = SW128(row * 128 + ks * 32 + (g >> 1) * 16);
    ldmx4(qH[ks], sb + A_OFF_QHI + off);
    ldmx4(qL[ks], sb + A_OFF_QLO + off);
  }

  float o[8][4];
#pragma unroll
  for (int dt = 0; dt < 8; dt++)
#pragma unroll
    for (int c = 0; c < 4; c++) o[dt][c] = 0.f;
  float m_i[2] = {-1e30f, -1e30f};
  float l_i[2] = {0.f, 0.f};

  for (int c = 0; c < 32; c++) {
    const int buf = c & 1;
    if (c < 31) {
      attn_load_chunk(sb, 1 - buf, (c + 1) * 64, tid, kh, kl, vh, vl);
      CP_COMMIT();
      CP_WAIT(1);
    } else {
      CP_WAIT(0);
    }
    __syncthreads();

    const uint32_t skh = sb + buf * A_STAGE + A_OFF_KHI;
    const uint32_t skl = sb + buf * A_STAGE + A_OFF_KLO;
    const uint32_t svh = sb + buf * A_STAGE + A_OFF_VHI;
    const uint32_t svl = sb + buf * A_STAGE + A_OFF_VLO;

    // ---- S = Q K^T (scaled: Q carries the 1/8) ----
    float s[8][4];
#pragma unroll
    for (int j = 0; j < 8; j++)
#pragma unroll
      for (int cc = 0; cc < 4; cc++) s[j][cc] = 0.f;

#pragma unroll
    for (int ks = 0; ks < 4; ks++) {
#pragma unroll
      for (int ng = 0; ng < 4; ng++) {
        uint32_t bkh[4], bkl[4];
        int row = ng * 16 + (g >> 1) * 8 + rr;
        uint32_t off = SW128(row * 128 + ks * 32 + (g & 1) * 16);
        ldmx4(bkh, skh + off);
        ldmx4(bkl, skl + off);
#pragma unroll
        for (int hf = 0; hf < 2; hf++) {
          const int j = ng * 2 + hf;
          mma16816(s[j], qH[ks], &bkh[hf * 2]);
          mma16816(s[j], qH[ks], &bkl[hf * 2]);
          mma16816(s[j], qL[ks], &bkh[hf * 2]);
        }
      }
    }

    // ---- online softmax (rows: l/4 and l/4+8) ----
#pragma unroll
    for (int r = 0; r < 2; r++) {
      float mx = -1e30f;
#pragma unroll
      for (int j = 0; j < 8; j++)
        mx = fmaxf(mx, fmaxf(s[j][2 * r], s[j][2 * r + 1]));
      mx = fmaxf(mx, __shfl_xor_sync(0xffffffffu, mx, 1));
      mx = fmaxf(mx, __shfl_xor_sync(0xffffffffu, mx, 2));
      float mnew = fmaxf(m_i[r], mx);
      float corr = __expf(m_i[r] - mnew);
      m_i[r] = mnew;
      float rs = 0.f;
#pragma unroll
      for (int j = 0; j < 8; j++) {
        float p0 = __expf(s[j][2 * r] - mnew);
        float p1 = __expf(s[j][2 * r + 1] - mnew);
        s[j][2 * r] = p0;
        s[j][2 * r + 1] = p1;
        rs += p0 + p1;
      }
      rs += __shfl_xor_sync(0xffffffffu, rs, 1);
      rs += __shfl_xor_sync(0xffffffffu, rs, 2);
      l_i[r] = l_i[r] * corr + rs;
#pragma unroll
      for (int dt = 0; dt < 8; dt++) {
        o[dt][2 * r] *= corr;
        o[dt][2 * r + 1] *= corr;
      }
    }

    // ---- O += P V ----
#pragma unroll
    for (int kk = 0; kk < 4; kk++) {
      uint32_t pH[4], pL[4];
      split2(s[2 * kk][0], s[2 * kk][1], pH[0], pL[0]);
      split2(s[2 * kk][2], s[2 * kk][3], pH[1], pL[1]);
      split2(s[2 * kk + 1][0], s[2 * kk + 1][1], pH[2], pL[2]);
      split2(s[2 * kk + 1][2], s[2 * kk + 1][3], pH[3], pL[3]);
#pragma unroll
      for (int dg = 0; dg < 4; dg++) {
        uint32_t bvh[4], bvl[4];
        int keyrow = kk * 16 + (g & 1) * 8 + rr;
        uint32_t off = SW128(keyrow * 128 + dg * 32 + (g >> 1) * 16);
        ldmx4t(bvh, svh + off);
        ldmx4t(bvl, svl + off);
#pragma unroll
        for (int hf = 0; hf < 2; hf++) {
          const int dt = dg * 2 + hf;
          mma16816(o[dt], pH, &bvh[hf * 2]);
          mma16816(o[dt], pH, &bvl[hf * 2]);
          mma16816(o[dt], pL, &bvh[hf * 2]);
        }
      }
    }
    __syncthreads();
  }

  // Epilogue: normalize, split to bf16 hi/lo, write scrambled ctx layout:
  //   ctx[b][h*128 + t/16][(t&15)*64 + d]
  const int b = bh >> 4;
  const int h = bh & 15;
#pragma unroll
  for (int r = 0; r < 2; r++) {
    const float inv = 1.0f / l_i[r];
    const int t = q0 + wid * 16 + (lane >> 2) + r * 8;
    const int row = h * 128 + (t >> 4);
    const size_t base = ((size_t)(b * Tn + row)) * En + ((t & 15) << 6);
#pragma unroll
    for (int dt = 0; dt < 8; dt++) {
      const int d = dt * 8 + (lane & 3) * 2;
      uint32_t hw, lw;
      split2(o[dt][2 * r] * inv, o[dt][2 * r + 1] * inv, hw, lw);
      *(uint32_t*)(gctx_hi + base + d) = hw;
      *(uint32_t*)(gctx_lo + base + d) = lw;
    }
  }
}

// ---------------------------------------------------------------------------
extern "C" void kernel_launch(void* const* d_in, const int* in_sizes, int n_in,
                              void* d_out, int out_size) {
  const float* x     = (const float*)d_in[0];  // (T, B, E)
  const float* w_in  = (const float*)d_in[1];  // (E, 3E)
  const float* b_in  = (const float*)d_in[2];  // (3E)
  const float* w_out = (const float*)d_in[3];  // (E, E)
  const float* b_out = (const float*)d_in[4];  // (E)
  float* out = (float*)d_out;                  // (B, T, E)

  cudaFuncSetAttribute(hmma_gemm, cudaFuncAttributeMaxDynamicSharedMemorySize,
                       GEMM_SMEM);
  cudaFuncSetAttribute(attn_hmma, cudaFuncAttributeMaxDynamicSharedMemorySize,
                       ATTN_SMEM);

  // bf16 split conversions
  cvt_x<<<(Mrows * Kdim / 4 + 255) / 256, 256>>>(x);
  cvt_transpose<<<dim3(Pn / 32, Kdim / 32), dim3(32, 8)>>>(w_in, 0);
  cvt_transpose<<<dim3(En / 32, Kdim / 32), dim3(32, 8)>>>(w_out, 1);

  // 1) QKV projection (HMMA) -> q/k/v bf16 splits (q pre-scaled 1/8)
  hmma_gemm<<<dim3(Pn / 128, Mrows / 128), 256, GEMM_SMEM>>>(b_in, nullptr, 0);
  // 2) Attention (HMMA flash) -> ctx bf16 splits
  attn_hmma<<<dim3(Tn / 128, BHn), 256, ATTN_SMEM>>>();
  // 3) Output projection (HMMA): M=4096, N=1024, K=1024
  hmma_gemm<<<dim3(En / 128, Mrows / 128), 256, GEMM_SMEM>>>(b_out, out, 1);
}